// round 3
// baseline (speedup 1.0000x reference)
#include <cuda_runtime.h>

#define N_NODES 100000
#define N_EDGES 1600000
#define F_IN 32
#define HID 16

// Scratch (no allocations allowed in kernel_launch)
__device__ __align__(16) float g_deg [N_NODES];
__device__ __align__(16) float g_xt  [N_NODES * HID];   // x @ W1_l.T
__device__ __align__(16) float g_sum1[N_NODES * HID];   // scatter target layer 1
__device__ __align__(16) float g_h   [N_NODES * HID];   // relu(layer1)
__device__ __align__(16) float g_sumh[N_NODES * HID];   // scatter target layer 2

// ---------------------------------------------------------------------------
// 0) zero scratch (must run every launch: graph replays reuse the buffers)
// ---------------------------------------------------------------------------
__global__ void k_zero() {
    int i = blockIdx.x * blockDim.x + threadIdx.x;
    int total = N_NODES * HID;
    if (i < total) {
        g_sum1[i] = 0.0f;
        g_sumh[i] = 0.0f;
    }
    if (i < N_NODES) g_deg[i] = 0.0f;
}

// ---------------------------------------------------------------------------
// 1) xt = x @ W1_l.T   (one thread per node, weights in shared)
// ---------------------------------------------------------------------------
__global__ void k_transform1(const float* __restrict__ x,
                             const float* __restrict__ W1l) {
    __shared__ float Ws[HID * F_IN];
    for (int i = threadIdx.x; i < HID * F_IN; i += blockDim.x) Ws[i] = W1l[i];
    __syncthreads();

    int n = blockIdx.x * blockDim.x + threadIdx.x;
    if (n >= N_NODES) return;

    float xr[F_IN];
    const float4* xp = reinterpret_cast<const float4*>(x + (size_t)n * F_IN);
#pragma unroll
    for (int q = 0; q < F_IN / 4; q++) {
        float4 v = xp[q];
        xr[4*q+0] = v.x; xr[4*q+1] = v.y; xr[4*q+2] = v.z; xr[4*q+3] = v.w;
    }

    float4* op = reinterpret_cast<float4*>(g_xt + (size_t)n * HID);
#pragma unroll
    for (int og = 0; og < HID / 4; og++) {
        float4 r;
        float* rp = &r.x;
#pragma unroll
        for (int oo = 0; oo < 4; oo++) {
            int o = og * 4 + oo;
            float acc = 0.0f;
#pragma unroll
            for (int k = 0; k < F_IN; k++) acc += xr[k] * Ws[o * F_IN + k];
            rp[oo] = acc;
        }
        op[og] = r;
    }
}

// ---------------------------------------------------------------------------
// 2) edge scatter layer 1: sum1[dst] += xt[src]; deg[dst] += 1
//    edge_index is int32 (JAX x64 disabled downcasts the int64 request)
// ---------------------------------------------------------------------------
__global__ void k_scatter1(const int* __restrict__ ei) {
    int e = blockIdx.x * blockDim.x + threadIdx.x;
    if (e >= N_EDGES) return;
    int s = ei[e];
    int d = ei[N_EDGES + e];

    atomicAdd(&g_deg[d], 1.0f);

    const float4* sp = reinterpret_cast<const float4*>(g_xt + (size_t)s * HID);
    float*        dp = g_sum1 + (size_t)d * HID;
#pragma unroll
    for (int q = 0; q < HID / 4; q++) {
        float4 v = sp[q];
        atomicAdd(dp + 4*q + 0, v.x);
        atomicAdd(dp + 4*q + 1, v.y);
        atomicAdd(dp + 4*q + 2, v.z);
        atomicAdd(dp + 4*q + 3, v.w);
    }
}

// ---------------------------------------------------------------------------
// 3) h = relu(sum1/max(deg,1) + b1 + x @ W1_r.T)
// ---------------------------------------------------------------------------
__global__ void k_node1(const float* __restrict__ x,
                        const float* __restrict__ b1,
                        const float* __restrict__ W1r) {
    __shared__ float Ws[HID * F_IN];
    __shared__ float bs[HID];
    for (int i = threadIdx.x; i < HID * F_IN; i += blockDim.x) Ws[i] = W1r[i];
    if (threadIdx.x < HID) bs[threadIdx.x] = b1[threadIdx.x];
    __syncthreads();

    int n = blockIdx.x * blockDim.x + threadIdx.x;
    if (n >= N_NODES) return;

    float inv = 1.0f / fmaxf(g_deg[n], 1.0f);

    float xr[F_IN];
    const float4* xp = reinterpret_cast<const float4*>(x + (size_t)n * F_IN);
#pragma unroll
    for (int q = 0; q < F_IN / 4; q++) {
        float4 v = xp[q];
        xr[4*q+0] = v.x; xr[4*q+1] = v.y; xr[4*q+2] = v.z; xr[4*q+3] = v.w;
    }

    float sr[HID];
    const float4* sp = reinterpret_cast<const float4*>(g_sum1 + (size_t)n * HID);
#pragma unroll
    for (int q = 0; q < HID / 4; q++) {
        float4 v = sp[q];
        sr[4*q+0] = v.x; sr[4*q+1] = v.y; sr[4*q+2] = v.z; sr[4*q+3] = v.w;
    }

    float4* op = reinterpret_cast<float4*>(g_h + (size_t)n * HID);
#pragma unroll
    for (int og = 0; og < HID / 4; og++) {
        float4 r;
        float* rp = &r.x;
#pragma unroll
        for (int oo = 0; oo < 4; oo++) {
            int o = og * 4 + oo;
            float acc = sr[o] * inv + bs[o];
#pragma unroll
            for (int k = 0; k < F_IN; k++) acc += xr[k] * Ws[o * F_IN + k];
            rp[oo] = fmaxf(acc, 0.0f);
        }
        op[og] = r;
    }
}

// ---------------------------------------------------------------------------
// 4) edge scatter layer 2: sumh[dst] += h[src]
// ---------------------------------------------------------------------------
__global__ void k_scatter2(const int* __restrict__ ei) {
    int e = blockIdx.x * blockDim.x + threadIdx.x;
    if (e >= N_EDGES) return;
    int s = ei[e];
    int d = ei[N_EDGES + e];

    const float4* sp = reinterpret_cast<const float4*>(g_h + (size_t)s * HID);
    float*        dp = g_sumh + (size_t)d * HID;
#pragma unroll
    for (int q = 0; q < HID / 4; q++) {
        float4 v = sp[q];
        atomicAdd(dp + 4*q + 0, v.x);
        atomicAdd(dp + 4*q + 1, v.y);
        atomicAdd(dp + 4*q + 2, v.z);
        atomicAdd(dp + 4*q + 3, v.w);
    }
}

// ---------------------------------------------------------------------------
// 5) out = (sumh/max(deg,1)) @ W2_l.T + b2 + h @ W2_r.T
// ---------------------------------------------------------------------------
__global__ void k_node2(float* __restrict__ out,
                        const float* __restrict__ W2l,
                        const float* __restrict__ b2,
                        const float* __restrict__ W2r) {
    __shared__ float Wl[F_IN * HID];
    __shared__ float Wr[F_IN * HID];
    __shared__ float bs[F_IN];
    for (int i = threadIdx.x; i < F_IN * HID; i += blockDim.x) {
        Wl[i] = W2l[i];
        Wr[i] = W2r[i];
    }
    if (threadIdx.x < F_IN) bs[threadIdx.x] = b2[threadIdx.x];
    __syncthreads();

    int n = blockIdx.x * blockDim.x + threadIdx.x;
    if (n >= N_NODES) return;

    float inv = 1.0f / fmaxf(g_deg[n], 1.0f);

    float hr[HID], ar[HID];
    const float4* hp = reinterpret_cast<const float4*>(g_h    + (size_t)n * HID);
    const float4* ap = reinterpret_cast<const float4*>(g_sumh + (size_t)n * HID);
#pragma unroll
    for (int q = 0; q < HID / 4; q++) {
        float4 v = hp[q];
        hr[4*q+0] = v.x; hr[4*q+1] = v.y; hr[4*q+2] = v.z; hr[4*q+3] = v.w;
        float4 a = ap[q];
        ar[4*q+0] = a.x * inv; ar[4*q+1] = a.y * inv;
        ar[4*q+2] = a.z * inv; ar[4*q+3] = a.w * inv;
    }

    float4* op = reinterpret_cast<float4*>(out + (size_t)n * F_IN);
#pragma unroll
    for (int fg = 0; fg < F_IN / 4; fg++) {
        float4 r;
        float* rp = &r.x;
#pragma unroll
        for (int ff = 0; ff < 4; ff++) {
            int f = fg * 4 + ff;
            float acc = bs[f];
#pragma unroll
            for (int k = 0; k < HID; k++) {
                acc += ar[k] * Wl[f * HID + k] + hr[k] * Wr[f * HID + k];
            }
            rp[ff] = acc;
        }
        op[fg] = r;
    }
}

// ---------------------------------------------------------------------------
extern "C" void kernel_launch(void* const* d_in, const int* in_sizes, int n_in,
                              void* d_out, int out_size) {
    const float* x   = (const float*)d_in[0];
    const int*   ei  = (const int*)d_in[1];   // [1,2,E], int32 (JAX x64 off)
    const float* W1l = (const float*)d_in[2];
    const float* b1  = (const float*)d_in[3];
    const float* W1r = (const float*)d_in[4];
    const float* W2l = (const float*)d_in[5];
    const float* b2  = (const float*)d_in[6];
    const float* W2r = (const float*)d_in[7];
    float*       out = (float*)d_out;

    const int T = 256;
    const int grid_nh   = (N_NODES * HID + T - 1) / T;
    const int grid_node = (N_NODES + T - 1) / T;
    const int grid_edge = (N_EDGES + T - 1) / T;

    k_zero      <<<grid_nh,   T>>>();
    k_transform1<<<grid_node, T>>>(x, W1l);
    k_scatter1  <<<grid_edge, T>>>(ei);
    k_node1     <<<grid_node, T>>>(x, b1, W1r);
    k_scatter2  <<<grid_edge, T>>>(ei);
    k_node2     <<<grid_node, T>>>(out, W2l, b2, W2r);
}

// round 4
// speedup vs baseline: 3.0731x; 3.0731x over previous
#include <cuda_runtime.h>

#define N_NODES 100000
#define N_EDGES 1600000
#define F_IN 32
#define HID 16

// Scratch (no allocations allowed in kernel_launch)
__device__ __align__(16) float g_deg [N_NODES];
__device__ __align__(16) float g_xt  [N_NODES * HID];   // x @ W1_l.T
__device__ __align__(16) float g_sum1[N_NODES * HID];   // scatter target layer 1
__device__ __align__(16) float g_h   [N_NODES * HID];   // relu(layer1)
__device__ __align__(16) float g_sumh[N_NODES * HID];   // scatter target layer 2

__device__ __forceinline__ void red_add_v4(float* addr, float4 v) {
    asm volatile("red.global.add.v4.f32 [%0], {%1,%2,%3,%4};"
                 :: "l"(addr), "f"(v.x), "f"(v.y), "f"(v.z), "f"(v.w)
                 : "memory");
}

// ---------------------------------------------------------------------------
// 0) zero scratch (must run every launch: graph replays reuse the buffers)
// ---------------------------------------------------------------------------
__global__ void k_zero() {
    int i = blockIdx.x * blockDim.x + threadIdx.x;
    int total = N_NODES * HID;
    if (i < total) {
        g_sum1[i] = 0.0f;
        g_sumh[i] = 0.0f;
    }
    if (i < N_NODES) g_deg[i] = 0.0f;
}

// ---------------------------------------------------------------------------
// 1) xt = x @ W1_l.T   (one thread per node, weights in shared)
// ---------------------------------------------------------------------------
__global__ void k_transform1(const float* __restrict__ x,
                             const float* __restrict__ W1l) {
    __shared__ float Ws[HID * F_IN];
    for (int i = threadIdx.x; i < HID * F_IN; i += blockDim.x) Ws[i] = W1l[i];
    __syncthreads();

    int n = blockIdx.x * blockDim.x + threadIdx.x;
    if (n >= N_NODES) return;

    float xr[F_IN];
    const float4* xp = reinterpret_cast<const float4*>(x + (size_t)n * F_IN);
#pragma unroll
    for (int q = 0; q < F_IN / 4; q++) {
        float4 v = xp[q];
        xr[4*q+0] = v.x; xr[4*q+1] = v.y; xr[4*q+2] = v.z; xr[4*q+3] = v.w;
    }

    float4* op = reinterpret_cast<float4*>(g_xt + (size_t)n * HID);
#pragma unroll
    for (int og = 0; og < HID / 4; og++) {
        float4 r;
        float* rp = &r.x;
#pragma unroll
        for (int oo = 0; oo < 4; oo++) {
            int o = og * 4 + oo;
            float acc = 0.0f;
#pragma unroll
            for (int k = 0; k < F_IN; k++) acc += xr[k] * Ws[o * F_IN + k];
            rp[oo] = acc;
        }
        op[og] = r;
    }
}

// ---------------------------------------------------------------------------
// 2) edge scatter layer 1: sum1[dst] += xt[src]; deg[dst] += 1
//    4 threads per edge, one red.v4 each.
// ---------------------------------------------------------------------------
__global__ void k_scatter1(const int* __restrict__ ei) {
    unsigned t = blockIdx.x * blockDim.x + threadIdx.x;
    unsigned e = t >> 2;
    unsigned q = t & 3;
    if (e >= N_EDGES) return;
    int s = __ldg(ei + e);
    int d = __ldg(ei + N_EDGES + e);

    if (q == 0) atomicAdd(&g_deg[d], 1.0f);

    float4 v = *reinterpret_cast<const float4*>(g_xt + (size_t)s * HID + q * 4);
    red_add_v4(g_sum1 + (size_t)d * HID + q * 4, v);
}

// ---------------------------------------------------------------------------
// 3) h = relu(sum1/max(deg,1) + b1 + x @ W1_r.T)
// ---------------------------------------------------------------------------
__global__ void k_node1(const float* __restrict__ x,
                        const float* __restrict__ b1,
                        const float* __restrict__ W1r) {
    __shared__ float Ws[HID * F_IN];
    __shared__ float bs[HID];
    for (int i = threadIdx.x; i < HID * F_IN; i += blockDim.x) Ws[i] = W1r[i];
    if (threadIdx.x < HID) bs[threadIdx.x] = b1[threadIdx.x];
    __syncthreads();

    int n = blockIdx.x * blockDim.x + threadIdx.x;
    if (n >= N_NODES) return;

    float inv = 1.0f / fmaxf(g_deg[n], 1.0f);

    float xr[F_IN];
    const float4* xp = reinterpret_cast<const float4*>(x + (size_t)n * F_IN);
#pragma unroll
    for (int q = 0; q < F_IN / 4; q++) {
        float4 v = xp[q];
        xr[4*q+0] = v.x; xr[4*q+1] = v.y; xr[4*q+2] = v.z; xr[4*q+3] = v.w;
    }

    float sr[HID];
    const float4* sp = reinterpret_cast<const float4*>(g_sum1 + (size_t)n * HID);
#pragma unroll
    for (int q = 0; q < HID / 4; q++) {
        float4 v = sp[q];
        sr[4*q+0] = v.x; sr[4*q+1] = v.y; sr[4*q+2] = v.z; sr[4*q+3] = v.w;
    }

    float4* op = reinterpret_cast<float4*>(g_h + (size_t)n * HID);
#pragma unroll
    for (int og = 0; og < HID / 4; og++) {
        float4 r;
        float* rp = &r.x;
#pragma unroll
        for (int oo = 0; oo < 4; oo++) {
            int o = og * 4 + oo;
            float acc = sr[o] * inv + bs[o];
#pragma unroll
            for (int k = 0; k < F_IN; k++) acc += xr[k] * Ws[o * F_IN + k];
            rp[oo] = fmaxf(acc, 0.0f);
        }
        op[og] = r;
    }
}

// ---------------------------------------------------------------------------
// 4) edge scatter layer 2: sumh[dst] += h[src]  (4 threads per edge)
// ---------------------------------------------------------------------------
__global__ void k_scatter2(const int* __restrict__ ei) {
    unsigned t = blockIdx.x * blockDim.x + threadIdx.x;
    unsigned e = t >> 2;
    unsigned q = t & 3;
    if (e >= N_EDGES) return;
    int s = __ldg(ei + e);
    int d = __ldg(ei + N_EDGES + e);

    float4 v = *reinterpret_cast<const float4*>(g_h + (size_t)s * HID + q * 4);
    red_add_v4(g_sumh + (size_t)d * HID + q * 4, v);
}

// ---------------------------------------------------------------------------
// 5) out = (sumh/max(deg,1)) @ W2_l.T + b2 + h @ W2_r.T
// ---------------------------------------------------------------------------
__global__ void k_node2(float* __restrict__ out,
                        const float* __restrict__ W2l,
                        const float* __restrict__ b2,
                        const float* __restrict__ W2r) {
    __shared__ float Wl[F_IN * HID];
    __shared__ float Wr[F_IN * HID];
    __shared__ float bs[F_IN];
    for (int i = threadIdx.x; i < F_IN * HID; i += blockDim.x) {
        Wl[i] = W2l[i];
        Wr[i] = W2r[i];
    }
    if (threadIdx.x < F_IN) bs[threadIdx.x] = b2[threadIdx.x];
    __syncthreads();

    int n = blockIdx.x * blockDim.x + threadIdx.x;
    if (n >= N_NODES) return;

    float inv = 1.0f / fmaxf(g_deg[n], 1.0f);

    float hr[HID], ar[HID];
    const float4* hp = reinterpret_cast<const float4*>(g_h    + (size_t)n * HID);
    const float4* ap = reinterpret_cast<const float4*>(g_sumh + (size_t)n * HID);
#pragma unroll
    for (int q = 0; q < HID / 4; q++) {
        float4 v = hp[q];
        hr[4*q+0] = v.x; hr[4*q+1] = v.y; hr[4*q+2] = v.z; hr[4*q+3] = v.w;
        float4 a = ap[q];
        ar[4*q+0] = a.x * inv; ar[4*q+1] = a.y * inv;
        ar[4*q+2] = a.z * inv; ar[4*q+3] = a.w * inv;
    }

    float4* op = reinterpret_cast<float4*>(out + (size_t)n * F_IN);
#pragma unroll
    for (int fg = 0; fg < F_IN / 4; fg++) {
        float4 r;
        float* rp = &r.x;
#pragma unroll
        for (int ff = 0; ff < 4; ff++) {
            int f = fg * 4 + ff;
            float acc = bs[f];
#pragma unroll
            for (int k = 0; k < HID; k++) {
                acc += ar[k] * Wl[f * HID + k] + hr[k] * Wr[f * HID + k];
            }
            rp[ff] = acc;
        }
        op[fg] = r;
    }
}

// ---------------------------------------------------------------------------
extern "C" void kernel_launch(void* const* d_in, const int* in_sizes, int n_in,
                              void* d_out, int out_size) {
    const float* x   = (const float*)d_in[0];
    const int*   ei  = (const int*)d_in[1];   // [1,2,E], int32 (JAX x64 off)
    const float* W1l = (const float*)d_in[2];
    const float* b1  = (const float*)d_in[3];
    const float* W1r = (const float*)d_in[4];
    const float* W2l = (const float*)d_in[5];
    const float* b2  = (const float*)d_in[6];
    const float* W2r = (const float*)d_in[7];
    float*       out = (float*)d_out;

    const int T = 256;
    const int grid_nh   = (N_NODES * HID + T - 1) / T;
    const int grid_node = (N_NODES + T - 1) / T;
    const int grid_edge4 = ((N_EDGES * 4) + T - 1) / T;

    k_zero      <<<grid_nh,   T>>>();
    k_transform1<<<grid_node, T>>>(x, W1l);
    k_scatter1  <<<grid_edge4, T>>>(ei);
    k_node1     <<<grid_node, T>>>(x, b1, W1r);
    k_scatter2  <<<grid_edge4, T>>>(ei);
    k_node2     <<<grid_node, T>>>(out, W2l, b2, W2r);
}

// round 5
// speedup vs baseline: 3.1891x; 1.0377x over previous
#include <cuda_runtime.h>

#define N_NODES 100000
#define N_EDGES 1600000
#define F_IN 32
#define HID 16

// Scratch (no allocations allowed in kernel_launch)
__device__ __align__(16) float g_deg [N_NODES];
__device__ __align__(16) float g_xt  [N_NODES * HID];   // x @ W1_l.T
__device__ __align__(16) float g_xr1 [N_NODES * HID];   // x @ W1_r.T
__device__ __align__(16) float g_sum1[N_NODES * HID];   // scatter target layer 1
__device__ __align__(16) float g_h   [N_NODES * HID];   // relu(layer1)
__device__ __align__(16) float g_sumh[N_NODES * HID];   // scatter target layer 2

__device__ __forceinline__ void red_add_v4(float* addr, float4 v) {
    asm volatile("red.global.add.v4.f32 [%0], {%1,%2,%3,%4};"
                 :: "l"(addr), "f"(v.x), "f"(v.y), "f"(v.z), "f"(v.w)
                 : "memory");
}

// ---------------------------------------------------------------------------
// 1) k_pre: per node — zero scratch rows, xt = x@W1l.T, xr1 = x@W1r.T
//    (one pass over x; zeroing fused so no separate k_zero launch)
// ---------------------------------------------------------------------------
__global__ void __launch_bounds__(256) k_pre(const float* __restrict__ x,
                                             const float* __restrict__ W1l,
                                             const float* __restrict__ W1r) {
    __shared__ float Wl[HID * F_IN];
    __shared__ float Wr[HID * F_IN];
    for (int i = threadIdx.x; i < HID * F_IN; i += blockDim.x) {
        Wl[i] = W1l[i];
        Wr[i] = W1r[i];
    }
    __syncthreads();

    int n = blockIdx.x * blockDim.x + threadIdx.x;
    if (n >= N_NODES) return;

    g_deg[n] = 0.0f;
    float4 z = make_float4(0.f, 0.f, 0.f, 0.f);
    float4* s1 = reinterpret_cast<float4*>(g_sum1 + (size_t)n * HID);
    float4* s2 = reinterpret_cast<float4*>(g_sumh + (size_t)n * HID);
#pragma unroll
    for (int q = 0; q < HID / 4; q++) { s1[q] = z; s2[q] = z; }

    float xr[F_IN];
    const float4* xp = reinterpret_cast<const float4*>(x + (size_t)n * F_IN);
#pragma unroll
    for (int q = 0; q < F_IN / 4; q++) {
        float4 v = xp[q];
        xr[4*q+0] = v.x; xr[4*q+1] = v.y; xr[4*q+2] = v.z; xr[4*q+3] = v.w;
    }

    float4* op_t = reinterpret_cast<float4*>(g_xt  + (size_t)n * HID);
    float4* op_r = reinterpret_cast<float4*>(g_xr1 + (size_t)n * HID);
#pragma unroll
    for (int og = 0; og < HID / 4; og++) {
        float4 rt, rr;
        float* rtp = &rt.x;
        float* rrp = &rr.x;
#pragma unroll
        for (int oo = 0; oo < 4; oo++) {
            int o = og * 4 + oo;
            float at = 0.0f, ar = 0.0f;
#pragma unroll
            for (int k = 0; k < F_IN; k++) {
                at += xr[k] * Wl[o * F_IN + k];
                ar += xr[k] * Wr[o * F_IN + k];
            }
            rtp[oo] = at;
            rrp[oo] = ar;
        }
        op_t[og] = rt;
        op_r[og] = rr;
    }
}

// ---------------------------------------------------------------------------
// 2) edge scatter layer 1: sum1[dst] += xt[src]; deg[dst] += 1
//    4 threads per edge, one red.v4 each.
// ---------------------------------------------------------------------------
__global__ void k_scatter1(const int* __restrict__ ei) {
    unsigned t = blockIdx.x * blockDim.x + threadIdx.x;
    unsigned e = t >> 2;
    unsigned q = t & 3;
    if (e >= N_EDGES) return;
    int s = __ldg(ei + e);
    int d = __ldg(ei + N_EDGES + e);

    if (q == 0) atomicAdd(&g_deg[d], 1.0f);

    float4 v = *reinterpret_cast<const float4*>(g_xt + (size_t)s * HID + q * 4);
    red_add_v4(g_sum1 + (size_t)d * HID + q * 4, v);
}

// ---------------------------------------------------------------------------
// 3) h = relu(sum1/max(deg,1) + b1 + xr1)   — pure elementwise, quad/node
// ---------------------------------------------------------------------------
__global__ void k_node1(const float* __restrict__ b1) {
    unsigned t = blockIdx.x * blockDim.x + threadIdx.x;
    unsigned n = t >> 2;
    unsigned q = t & 3;
    if (n >= N_NODES) return;

    float inv = 1.0f / fmaxf(__ldg(&g_deg[n]), 1.0f);
    float4 s = *reinterpret_cast<const float4*>(g_sum1 + (size_t)n * HID + q * 4);
    float4 r = *reinterpret_cast<const float4*>(g_xr1  + (size_t)n * HID + q * 4);
    float4 b = __ldg(reinterpret_cast<const float4*>(b1) + q);

    float4 o;
    o.x = fmaxf(s.x * inv + b.x + r.x, 0.0f);
    o.y = fmaxf(s.y * inv + b.y + r.y, 0.0f);
    o.z = fmaxf(s.z * inv + b.z + r.z, 0.0f);
    o.w = fmaxf(s.w * inv + b.w + r.w, 0.0f);
    *reinterpret_cast<float4*>(g_h + (size_t)n * HID + q * 4) = o;
}

// ---------------------------------------------------------------------------
// 4) edge scatter layer 2: sumh[dst] += h[src]  (4 threads per edge)
// ---------------------------------------------------------------------------
__global__ void k_scatter2(const int* __restrict__ ei) {
    unsigned t = blockIdx.x * blockDim.x + threadIdx.x;
    unsigned e = t >> 2;
    unsigned q = t & 3;
    if (e >= N_EDGES) return;
    int s = __ldg(ei + e);
    int d = __ldg(ei + N_EDGES + e);

    float4 v = *reinterpret_cast<const float4*>(g_h + (size_t)s * HID + q * 4);
    red_add_v4(g_sumh + (size_t)d * HID + q * 4, v);
}

// ---------------------------------------------------------------------------
// 5) out = (sumh/max(deg,1)) @ W2_l.T + b2 + h @ W2_r.T
// ---------------------------------------------------------------------------
__global__ void __launch_bounds__(256) k_node2(float* __restrict__ out,
                        const float* __restrict__ W2l,
                        const float* __restrict__ b2,
                        const float* __restrict__ W2r) {
    __shared__ float Wl[F_IN * HID];
    __shared__ float Wr[F_IN * HID];
    __shared__ float bs[F_IN];
    for (int i = threadIdx.x; i < F_IN * HID; i += blockDim.x) {
        Wl[i] = W2l[i];
        Wr[i] = W2r[i];
    }
    if (threadIdx.x < F_IN) bs[threadIdx.x] = b2[threadIdx.x];
    __syncthreads();

    int n = blockIdx.x * blockDim.x + threadIdx.x;
    if (n >= N_NODES) return;

    float inv = 1.0f / fmaxf(g_deg[n], 1.0f);

    float hr[HID], ar[HID];
    const float4* hp = reinterpret_cast<const float4*>(g_h    + (size_t)n * HID);
    const float4* ap = reinterpret_cast<const float4*>(g_sumh + (size_t)n * HID);
#pragma unroll
    for (int q = 0; q < HID / 4; q++) {
        float4 v = hp[q];
        hr[4*q+0] = v.x; hr[4*q+1] = v.y; hr[4*q+2] = v.z; hr[4*q+3] = v.w;
        float4 a = ap[q];
        ar[4*q+0] = a.x * inv; ar[4*q+1] = a.y * inv;
        ar[4*q+2] = a.z * inv; ar[4*q+3] = a.w * inv;
    }

    float4* op = reinterpret_cast<float4*>(out + (size_t)n * F_IN);
#pragma unroll
    for (int fg = 0; fg < F_IN / 4; fg++) {
        float4 r;
        float* rp = &r.x;
#pragma unroll
        for (int ff = 0; ff < 4; ff++) {
            int f = fg * 4 + ff;
            float acc = bs[f];
#pragma unroll
            for (int k = 0; k < HID; k++) {
                acc += ar[k] * Wl[f * HID + k] + hr[k] * Wr[f * HID + k];
            }
            rp[ff] = acc;
        }
        op[fg] = r;
    }
}

// ---------------------------------------------------------------------------
extern "C" void kernel_launch(void* const* d_in, const int* in_sizes, int n_in,
                              void* d_out, int out_size) {
    const float* x   = (const float*)d_in[0];
    const int*   ei  = (const int*)d_in[1];   // [1,2,E], int32 (JAX x64 off)
    const float* W1l = (const float*)d_in[2];
    const float* b1  = (const float*)d_in[3];
    const float* W1r = (const float*)d_in[4];
    const float* W2l = (const float*)d_in[5];
    const float* b2  = (const float*)d_in[6];
    const float* W2r = (const float*)d_in[7];
    float*       out = (float*)d_out;

    const int T = 256;
    const int grid_node  = (N_NODES + T - 1) / T;
    const int grid_node4 = (N_NODES * 4 + T - 1) / T;
    const int grid_edge4 = ((N_EDGES * 4) + T - 1) / T;

    k_pre     <<<grid_node,  T>>>(x, W1l, W1r);
    k_scatter1<<<grid_edge4, T>>>(ei);
    k_node1   <<<grid_node4, T>>>(b1);
    k_scatter2<<<grid_edge4, T>>>(ei);
    k_node2   <<<grid_node,  T>>>(out, W2l, b2, W2r);
}